// round 11
// baseline (speedup 1.0000x reference)
#include <cuda_runtime.h>
#include <cuda_fp16.h>
#include <cuda_bf16.h>
#include <mma.h>
#include <stdint.h>

using namespace nvcuda;

// ---------------- problem constants ----------------
#define NMAX 50000
#define EMAX 800000
#define D    128
#define TSTRIDE 40                 // smem tile stride (halves): 80B rows
#define BK 32
#define TILE_B 10240u              // one 128xBK fp16 tile, stride 40
#define AGG_OFF(c)  ((c) * TILE_B)                 // aggT chunks 0..3: [0, 40960)
#define WST_OFF(b)  (40960u + (b) * TILE_B)        // Wl stage: [40960, 61440)
#define AWST_OFF(b) ((b) * 2u * TILE_B)            // src1 A+W stage: [0, 40960)
#define SMEM_TOTAL 65536                           // Csm (128*128*4) dominates

// ---------------- device scratch ----------------
__device__ int   g_cnt[NMAX];
__device__ int   g_rp[NMAX];
__device__ float g_inv[NMAX];
__device__ int   g_col[EMAX];
__device__ int   g_slot[EMAX];
__device__ int   g_tot;
__device__ int   g_is64;
__device__ __align__(16) __half g_act[NMAX * D];    // activation ping
__device__ __align__(16) __half g_act2[NMAX * D];   // activation pong
__device__ __align__(16) __half g_W[6 * D * D];     // fp16 weights

// ---------------- helpers ----------------
__device__ __forceinline__ unsigned smem_u32(const void* p) {
    unsigned a;
    asm("{ .reg .u64 t; cvta.to.shared.u64 t, %1; cvt.u32.u64 %0, t; }"
        : "=r"(a) : "l"(p));
    return a;
}

__device__ __forceinline__ void cp16(unsigned sdst, const void* gsrc) {
    asm volatile("cp.async.cg.shared.global [%0], [%1], 16;"
                 :: "r"(sdst), "l"(gsrc));
}

// ---------------- edge-index dtype detection ----------------
__global__ void detect_kernel(const void* ei, int E) {
    const int* p = (const int*)ei;
    int t = threadIdx.x;
    int m = min(E, 2048);
    int bad = 0;
    for (int i = t; i < m; i += blockDim.x) bad |= p[2 * i + 1];
    __shared__ int s;
    if (t == 0) s = 0;
    __syncthreads();
    atomicOr(&s, bad);
    __syncthreads();
    if (t == 0) g_is64 = (s == 0) ? 1 : 0;
}

__device__ __forceinline__ int load_idx(const void* ei, long long pos) {
    if (g_is64) return (int)((const long long*)ei)[pos];
    return ((const int*)ei)[pos];
}

// ---------------- CSR build ----------------
__global__ void hist_kernel(const void* ei, int E) {
    int e0 = 4 * (blockIdx.x * blockDim.x + threadIdx.x);
    if (e0 >= E) return;
    int cnt = min(4, E - e0);
    int d[4], sl[4];
    #pragma unroll
    for (int i = 0; i < 4; ++i)
        if (i < cnt) d[i] = load_idx(ei, (long long)E + e0 + i);
    #pragma unroll
    for (int i = 0; i < 4; ++i)
        if (i < cnt) sl[i] = atomicAdd(&g_cnt[d[i]], 1);
    #pragma unroll
    for (int i = 0; i < 4; ++i)
        if (i < cnt) g_slot[e0 + i] = sl[i];
}

__global__ void assign_kernel(int n) {
    int i = blockIdx.x * blockDim.x + threadIdx.x;
    int lane = threadIdx.x & 31;
    int c = (i < n) ? g_cnt[i] : 0;
    int x = c;
    #pragma unroll
    for (int off = 1; off < 32; off <<= 1) {
        int y = __shfl_up_sync(0xffffffffu, x, off);
        if (lane >= off) x += y;
    }
    int wsum = __shfl_sync(0xffffffffu, x, 31);
    int base = 0;
    if (lane == 31) base = atomicAdd(&g_tot, wsum);
    base = __shfl_sync(0xffffffffu, base, 31);
    int excl = base + x - c;
    if (i < n) {
        g_rp[i]  = excl;
        g_inv[i] = 1.0f / ((c > 0) ? (float)c : 1.0f);
    }
}

__global__ void fill_kernel(const void* ei, int E) {
    int e0 = 4 * (blockIdx.x * blockDim.x + threadIdx.x);
    if (e0 >= E) return;
    int cnt = min(4, E - e0);
    int s[4], d[4], sl[4], rp[4];
    #pragma unroll
    for (int i = 0; i < 4; ++i)
        if (i < cnt) {
            s[i]  = load_idx(ei, e0 + i);
            d[i]  = load_idx(ei, (long long)E + e0 + i);
            sl[i] = g_slot[e0 + i];
        }
    #pragma unroll
    for (int i = 0; i < 4; ++i)
        if (i < cnt) rp[i] = g_rp[d[i]];
    #pragma unroll
    for (int i = 0; i < 4; ++i)
        if (i < cnt) g_col[rp[i] + sl[i]] = s[i];
}

// ---------------- conversions ----------------
__global__ void xconv_kernel(const float* __restrict__ x,
                             __half* __restrict__ act, int total4) {
    int i = blockIdx.x * blockDim.x + threadIdx.x;
    if (i >= total4) return;
    float4 v = *(const float4*)(x + 4 * i);
    __half2 a0 = __floats2half2_rn(v.x, v.y);
    __half2 a1 = __floats2half2_rn(v.z, v.w);
    *(uint2*)(act + 4 * i) = make_uint2(*(unsigned*)&a0, *(unsigned*)&a1);
}

__global__ void wconv_kernel(const float* __restrict__ w0, const float* __restrict__ w1,
                             const float* __restrict__ w2, const float* __restrict__ w3,
                             const float* __restrict__ w4, const float* __restrict__ w5) {
    int i = blockIdx.x * blockDim.x + threadIdx.x;
    if (i >= 6 * D * D) return;
    int m = i >> 14, off = i & (D * D - 1);
    const float* src;
    switch (m) {
        case 0: src = w0; break; case 1: src = w1; break;
        case 2: src = w2; break; case 3: src = w3; break;
        case 4: src = w4; break; default: src = w5; break;
    }
    g_W[i] = __float2half_rn(src[off]);
}

// ---------------- fused agg + GEMM ----------------
// Phase A: this block's 128 rows are mean-aggregated (fp16 gather from act_in,
//          fp32 acc) into 4 smem k-chunk tiles (aggT).
// Phase B: out = [relu]( agg@Wl^T + act_in@Wr^T + b ); 8 chunks:
//          c<4 : A from aggT[c] (smem), W = Wl chunk staged (overlaps phase A)
//          c>=4: A = act_in chunk + W = Wr chunk, staged into reused aggT space.
__device__ __forceinline__ void acc_add(float4& acc, uint2 v) {
    __half2 h0 = *(__half2*)&v.x;
    __half2 h1 = *(__half2*)&v.y;
    float2 f0 = __half22float2(h0);
    float2 f1 = __half22float2(h1);
    acc.x += f0.x; acc.y += f0.y; acc.z += f1.x; acc.w += f1.y;
}

__global__ __launch_bounds__(256)
void fused_kernel(const __half* __restrict__ Act,
                  const __half* __restrict__ Wl, const __half* __restrict__ Wr,
                  const float* __restrict__ bias,
                  float* __restrict__ out, __half* __restrict__ actout,
                  int n, int relu, int fin) {
    extern __shared__ char smraw[];
    float* Csm = (float*)smraw;

    int tid = threadIdx.x;
    int wid = tid >> 5;
    int lane = tid & 31;
    int warp_m = wid & 3;
    int warp_n = wid >> 2;
    int m0 = blockIdx.x * 128;

    int lrow = tid >> 1;          // 0..127 (staging row)
    int lcol = (tid & 1) * 16;    // 0 or 16
    int grow = m0 + lrow;
    int arow = (grow < n) ? grow : (n - 1);
    unsigned soff = (unsigned)(lrow * TSTRIDE + lcol) * 2;
    unsigned sbase = smem_u32(smraw);

    // issue staging for chunk c into its buffer
    #define ISSUE(c) do {                                                       \
        if ((c) < 4) {                                                          \
            int k0_ = (c) * BK;                                                 \
            unsigned dst_ = sbase + WST_OFF((c) & 1) + soff;                    \
            size_t gw_ = (size_t)lrow * D + k0_ + lcol;                         \
            cp16(dst_,      Wl + gw_);                                          \
            cp16(dst_ + 16, Wl + gw_ + 8);                                      \
        } else {                                                                \
            int k0_ = ((c) - 4) * BK;                                           \
            unsigned bb_ = sbase + AWST_OFF((c) & 1);                           \
            size_t ga_ = (size_t)arow * D + k0_ + lcol;                         \
            size_t gw_ = (size_t)lrow * D + k0_ + lcol;                         \
            cp16(bb_ + soff,                 Act + ga_);                        \
            cp16(bb_ + soff + 16,            Act + ga_ + 8);                    \
            cp16(bb_ + TILE_B + soff,        Wr + gw_);                         \
            cp16(bb_ + TILE_B + soff + 16,   Wr + gw_ + 8);                     \
        }                                                                       \
        asm volatile("cp.async.commit_group;");                                 \
    } while (0)

    // prefetch Wl chunk 0 — lands while phase A gathers
    ISSUE(0);

    // ---------- Phase A: aggregate 16 rows per warp into aggT ----------
    {
        int chunk = lane >> 3;                 // which 32-K tile
        int coff  = (lane & 7) * 4;            // half offset inside tile row
        #pragma unroll 1
        for (int k = 0; k < 16; ++k) {
            int r = wid * 16 + k;
            int node = m0 + r;
            float4 acc = make_float4(0.f, 0.f, 0.f, 0.f);
            float inv = 0.f;
            if (node < n) {
                int start = g_rp[node];
                int end   = start + g_cnt[node];
                inv = g_inv[node];
                for (int e = start; e < end; e += 32) {
                    int myc = (e + lane < end) ? g_col[e + lane] : 0;
                    int m = min(32, end - e);
                    int j = 0;
                    for (; j + 4 <= m; j += 4) {
                        int s0 = __shfl_sync(0xffffffffu, myc, j + 0);
                        int s1 = __shfl_sync(0xffffffffu, myc, j + 1);
                        int s2 = __shfl_sync(0xffffffffu, myc, j + 2);
                        int s3 = __shfl_sync(0xffffffffu, myc, j + 3);
                        uint2 v0 = *(const uint2*)(Act + (size_t)s0 * D + 4 * lane);
                        uint2 v1 = *(const uint2*)(Act + (size_t)s1 * D + 4 * lane);
                        uint2 v2 = *(const uint2*)(Act + (size_t)s2 * D + 4 * lane);
                        uint2 v3 = *(const uint2*)(Act + (size_t)s3 * D + 4 * lane);
                        acc_add(acc, v0); acc_add(acc, v1);
                        acc_add(acc, v2); acc_add(acc, v3);
                    }
                    for (; j < m; ++j) {
                        int s = __shfl_sync(0xffffffffu, myc, j);
                        uint2 v = *(const uint2*)(Act + (size_t)s * D + 4 * lane);
                        acc_add(acc, v);
                    }
                }
            }
            __half2 p0 = __floats2half2_rn(acc.x * inv, acc.y * inv);
            __half2 p1 = __floats2half2_rn(acc.z * inv, acc.w * inv);
            *(uint2*)(smraw + AGG_OFF(chunk) + (unsigned)(r * TSTRIDE + coff) * 2) =
                make_uint2(*(unsigned*)&p0, *(unsigned*)&p1);
        }
    }

    // ---------- Phase B: MMA over 8 chunks ----------
    wmma::fragment<wmma::accumulator, 16, 16, 16, float> acc[2][4];
    #pragma unroll
    for (int i = 0; i < 2; ++i)
        #pragma unroll
        for (int j = 0; j < 4; ++j) wmma::fill_fragment(acc[i][j], 0.0f);

    for (int c = 0; c < 8; ++c) {
        asm volatile("cp.async.wait_group 0;");
        __syncthreads();
        if (c < 7) ISSUE(c + 1);

        __half* As;
        __half* Ws;
        if (c < 4) {
            As = (__half*)(smraw + AGG_OFF(c));
            Ws = (__half*)(smraw + WST_OFF(c & 1));
        } else {
            As = (__half*)(smraw + AWST_OFF(c & 1));
            Ws = As + TILE_B / 2;
        }

        #pragma unroll
        for (int kk = 0; kk < BK; kk += 16) {
            wmma::fragment<wmma::matrix_a, 16, 16, 16, __half, wmma::row_major> a[2];
            #pragma unroll
            for (int i = 0; i < 2; ++i)
                wmma::load_matrix_sync(a[i], As + (warp_m * 32 + i * 16) * TSTRIDE + kk, TSTRIDE);
            #pragma unroll
            for (int j = 0; j < 4; ++j) {
                wmma::fragment<wmma::matrix_b, 16, 16, 16, __half, wmma::col_major> b;
                wmma::load_matrix_sync(b, Ws + (warp_n * 64 + j * 16) * TSTRIDE + kk, TSTRIDE);
                #pragma unroll
                for (int i = 0; i < 2; ++i)
                    wmma::mma_sync(acc[i][j], a[i], b, acc[i][j]);
            }
        }
    }
    __syncthreads();
    #pragma unroll
    for (int i = 0; i < 2; ++i)
        #pragma unroll
        for (int j = 0; j < 4; ++j)
            wmma::store_matrix_sync(Csm + (warp_m * 32 + i * 16) * 128 + warp_n * 64 + j * 16,
                                    acc[i][j], 128, wmma::mem_row_major);
    __syncthreads();

    #pragma unroll
    for (int it = 0; it < 16; ++it) {
        int e = (it * 256 + tid) * 4;
        int row = e >> 7;
        int col = e & 127;
        int gr = m0 + row;
        if (gr >= n) continue;
        float4 v = *(float4*)(Csm + e);
        float4 b = *(const float4*)(bias + col);
        v.x += b.x; v.y += b.y; v.z += b.z; v.w += b.w;
        if (relu) {
            v.x = fmaxf(v.x, 0.f); v.y = fmaxf(v.y, 0.f);
            v.z = fmaxf(v.z, 0.f); v.w = fmaxf(v.w, 0.f);
        }
        size_t go = (size_t)gr * D + col;
        if (fin) {
            *(float4*)(out + go) = v;
        } else {
            __half2 a0 = __floats2half2_rn(v.x, v.y);
            __half2 a1 = __floats2half2_rn(v.z, v.w);
            *(uint2*)(actout + go) = make_uint2(*(unsigned*)&a0, *(unsigned*)&a1);
        }
    }
}

// ---------------- launch ----------------
extern "C" void kernel_launch(void* const* d_in, const int* in_sizes, int n_in,
                              void* d_out, int out_size) {
    const float* x   = (const float*)d_in[0];
    const void*  ei  = d_in[1];
    const float* W1l = (const float*)d_in[2];
    const float* b1  = (const float*)d_in[3];
    const float* W1r = (const float*)d_in[4];
    const float* W2l = (const float*)d_in[5];
    const float* b2  = (const float*)d_in[6];
    const float* W2r = (const float*)d_in[7];
    const float* W3l = (const float*)d_in[8];
    const float* b3  = (const float*)d_in[9];
    const float* W3r = (const float*)d_in[10];
    float* out = (float*)d_out;

    int n = in_sizes[0] / D;
    int E = in_sizes[1] / 2;

    __half *actA, *actB, *wp;
    int *cntp, *totp;
    cudaGetSymbolAddress((void**)&actA, g_act);
    cudaGetSymbolAddress((void**)&actB, g_act2);
    cudaGetSymbolAddress((void**)&wp,   g_W);
    cudaGetSymbolAddress((void**)&cntp, g_cnt);
    cudaGetSymbolAddress((void**)&totp, g_tot);

    cudaFuncSetAttribute(fused_kernel, cudaFuncAttributeMaxDynamicSharedMemorySize, SMEM_TOTAL);

    // CSR build
    detect_kernel<<<1, 256>>>(ei, E);
    cudaMemsetAsync(cntp, 0, (size_t)n * sizeof(int));
    cudaMemsetAsync(totp, 0, sizeof(int));
    int e4 = (E + 3) / 4;
    hist_kernel<<<(e4 + 255) / 256, 256>>>(ei, E);
    assign_kernel<<<(n + 255) / 256, 256>>>(n);
    fill_kernel<<<(e4 + 255) / 256, 256>>>(ei, E);

    // conversions
    wconv_kernel<<<(6 * D * D + 255) / 256, 256>>>(W1l, W1r, W2l, W2r, W3l, W3r);
    int total4 = n * D / 4;
    xconv_kernel<<<(total4 + 255) / 256, 256>>>(x, actA, total4);

    int blocks = (n + 127) / 128;

    // layer 1: actA -> actB
    fused_kernel<<<blocks, 256, SMEM_TOTAL>>>(actA,
        wp + 0 * D * D, wp + 1 * D * D, b1, out, actB, n, 1, 0);
    // layer 2: actB -> actA
    fused_kernel<<<blocks, 256, SMEM_TOTAL>>>(actB,
        wp + 2 * D * D, wp + 3 * D * D, b2, out, actA, n, 1, 0);
    // layer 3: actA -> out (fp32)
    fused_kernel<<<blocks, 256, SMEM_TOTAL>>>(actA,
        wp + 4 * D * D, wp + 5 * D * D, b3, out, actA, n, 0, 1);
}

// round 12
// speedup vs baseline: 1.4098x; 1.4098x over previous
#include <cuda_runtime.h>
#include <cuda_fp16.h>
#include <cuda_bf16.h>
#include <mma.h>
#include <stdint.h>

using namespace nvcuda;

// ---------------- problem constants ----------------
#define NMAX 50000
#define EMAX 800000
#define D    128
#define TSTRIDE 40        // smem tile stride (halves): 80B rows
#define BK 32
#define TILE_BYTES (128 * TSTRIDE * 2)      // 10240 B per fp16 tile
#define BUF_BYTES  (2 * TILE_BYTES)         // 20480 B per stage (A, W)
#define SMEM_TOTAL 65536                    // Csm (128*128*4) dominates

// ---------------- device scratch ----------------
__device__ int   g_cnt[NMAX];
__device__ int   g_rp[NMAX];
__device__ float g_inv[NMAX];
__device__ int   g_col[EMAX];
__device__ int   g_slot[EMAX];
__device__ int   g_tot;
__device__ int   g_is64;
__device__ __align__(16) __half g_act[NMAX * D];   // fp16 activations
__device__ __align__(16) __half g_agg[NMAX * D];   // fp16 aggregated means
__device__ __align__(16) __half g_W[6 * D * D];    // fp16 weights

// ---------------- helpers ----------------
__device__ __forceinline__ unsigned smem_u32(const void* p) {
    unsigned a;
    asm("{ .reg .u64 t; cvta.to.shared.u64 t, %1; cvt.u32.u64 %0, t; }"
        : "=r"(a) : "l"(p));
    return a;
}

__device__ __forceinline__ void cp16(unsigned sdst, const void* gsrc) {
    asm volatile("cp.async.cg.shared.global [%0], [%1], 16;"
                 :: "r"(sdst), "l"(gsrc));
}

// ---------------- edge-index dtype detection ----------------
__global__ void detect_kernel(const void* ei, int E) {
    const int* p = (const int*)ei;
    int t = threadIdx.x;
    int m = min(E, 2048);
    int bad = 0;
    for (int i = t; i < m; i += blockDim.x) bad |= p[2 * i + 1];
    __shared__ int s;
    if (t == 0) s = 0;
    __syncthreads();
    atomicOr(&s, bad);
    __syncthreads();
    if (t == 0) g_is64 = (s == 0) ? 1 : 0;
}

__device__ __forceinline__ int load_idx(const void* ei, long long pos) {
    if (g_is64) return (int)((const long long*)ei)[pos];
    return ((const int*)ei)[pos];
}

// ---------------- CSR build ----------------
// hist: count per dst AND record each edge's within-segment slot (atomic return).
__global__ void hist_kernel(const void* ei, int E) {
    int e0 = 4 * (blockIdx.x * blockDim.x + threadIdx.x);
    if (e0 >= E) return;
    int cnt = min(4, E - e0);
    int d[4], sl[4];
    #pragma unroll
    for (int i = 0; i < 4; ++i)
        if (i < cnt) d[i] = load_idx(ei, (long long)E + e0 + i);
    #pragma unroll
    for (int i = 0; i < 4; ++i)
        if (i < cnt) sl[i] = atomicAdd(&g_cnt[d[i]], 1);
    #pragma unroll
    for (int i = 0; i < 4; ++i)
        if (i < cnt) g_slot[e0 + i] = sl[i];
}

__global__ void assign_kernel(int n) {
    int i = blockIdx.x * blockDim.x + threadIdx.x;
    int lane = threadIdx.x & 31;
    int c = (i < n) ? g_cnt[i] : 0;
    int x = c;
    #pragma unroll
    for (int off = 1; off < 32; off <<= 1) {
        int y = __shfl_up_sync(0xffffffffu, x, off);
        if (lane >= off) x += y;
    }
    int wsum = __shfl_sync(0xffffffffu, x, 31);
    int base = 0;
    if (lane == 31) base = atomicAdd(&g_tot, wsum);
    base = __shfl_sync(0xffffffffu, base, 31);
    int excl = base + x - c;
    if (i < n) {
        g_rp[i]  = excl;
        g_inv[i] = 1.0f / ((c > 0) ? (float)c : 1.0f);
    }
}

// fill: no atomics — slot was recorded by hist.
__global__ void fill_kernel(const void* ei, int E) {
    int e0 = 4 * (blockIdx.x * blockDim.x + threadIdx.x);
    if (e0 >= E) return;
    int cnt = min(4, E - e0);
    int s[4], d[4], sl[4], rp[4];
    #pragma unroll
    for (int i = 0; i < 4; ++i)
        if (i < cnt) {
            s[i]  = load_idx(ei, e0 + i);
            d[i]  = load_idx(ei, (long long)E + e0 + i);
            sl[i] = g_slot[e0 + i];
        }
    #pragma unroll
    for (int i = 0; i < 4; ++i)
        if (i < cnt) rp[i] = g_rp[d[i]];
    #pragma unroll
    for (int i = 0; i < 4; ++i)
        if (i < cnt) g_col[rp[i] + sl[i]] = s[i];
}

// ---------------- conversions (weights + input, one launch) ----------------
__global__ void conv_kernel(const float* __restrict__ x, __half* __restrict__ act,
                            int total4,
                            const float* __restrict__ w0, const float* __restrict__ w1,
                            const float* __restrict__ w2, const float* __restrict__ w3,
                            const float* __restrict__ w4, const float* __restrict__ w5) {
    int i = blockIdx.x * blockDim.x + threadIdx.x;
    if (i < 6 * D * D) {
        int m = i >> 14, off = i & (D * D - 1);
        const float* src;
        switch (m) {
            case 0: src = w0; break; case 1: src = w1; break;
            case 2: src = w2; break; case 3: src = w3; break;
            case 4: src = w4; break; default: src = w5; break;
        }
        g_W[i] = __float2half_rn(src[off]);
    }
    int j = i - 6 * D * D;
    if (j >= 0 && j < total4) {
        float4 v = *(const float4*)(x + 4 * j);
        __half2 a0 = __floats2half2_rn(v.x, v.y);
        __half2 a1 = __floats2half2_rn(v.z, v.w);
        *(uint2*)(act + 4 * j) = make_uint2(*(unsigned*)&a0, *(unsigned*)&a1);
    }
}

// ---------------- mean aggregation: half-warp pairs, LDG.128 ----------------
// Lanes 0-15 process even edges, lanes 16-31 odd edges; each 16-lane group
// covers one full 256B row with uint4 loads. Final cross-half shfl reduction.
__device__ __forceinline__ void add8(float4& a0, float4& a1, uint4 v) {
    __half2 h0 = *(__half2*)&v.x;
    __half2 h1 = *(__half2*)&v.y;
    __half2 h2 = *(__half2*)&v.z;
    __half2 h3 = *(__half2*)&v.w;
    float2 f0 = __half22float2(h0);
    float2 f1 = __half22float2(h1);
    float2 f2 = __half22float2(h2);
    float2 f3 = __half22float2(h3);
    a0.x += f0.x; a0.y += f0.y; a0.z += f1.x; a0.w += f1.y;
    a1.x += f2.x; a1.y += f2.y; a1.z += f3.x; a1.w += f3.y;
}

__global__ void agg_kernel(const __half* __restrict__ hin,
                           __half* __restrict__ aout, int n) {
    int w = (blockIdx.x * blockDim.x + threadIdx.x) >> 5;
    int lane = threadIdx.x & 31;
    if (w >= n) return;
    int start = g_rp[w];
    int end = start + g_cnt[w];
    int half = lane >> 4;        // which edge of the pair
    int li   = lane & 15;        // column group: halves [8*li, 8*li+8)
    const __half* base = hin + 8 * li;
    float4 a0 = make_float4(0.f, 0.f, 0.f, 0.f);
    float4 a1 = make_float4(0.f, 0.f, 0.f, 0.f);

    for (int e = start; e < end; e += 32) {
        int myc = (e + lane < end) ? g_col[e + lane] : 0;
        int m = min(32, end - e);
        int j = 0;
        for (; j + 4 <= m; j += 4) {
            int sA = __shfl_sync(0xffffffffu, myc, j + half);
            int sB = __shfl_sync(0xffffffffu, myc, j + 2 + half);
            uint4 vA = *(const uint4*)(base + (size_t)sA * D);
            uint4 vB = *(const uint4*)(base + (size_t)sB * D);
            add8(a0, a1, vA);
            add8(a0, a1, vB);
        }
        for (; j < m; j += 2) {
            int idx = j + half;
            int safe = (idx < m) ? idx : j;
            int s = __shfl_sync(0xffffffffu, myc, safe);
            uint4 v = *(const uint4*)(base + (size_t)s * D);
            if (idx < m) add8(a0, a1, v);
        }
    }

    // cross-half reduction: lane i += lane i+16
    a0.x += __shfl_xor_sync(0xffffffffu, a0.x, 16);
    a0.y += __shfl_xor_sync(0xffffffffu, a0.y, 16);
    a0.z += __shfl_xor_sync(0xffffffffu, a0.z, 16);
    a0.w += __shfl_xor_sync(0xffffffffu, a0.w, 16);
    a1.x += __shfl_xor_sync(0xffffffffu, a1.x, 16);
    a1.y += __shfl_xor_sync(0xffffffffu, a1.y, 16);
    a1.z += __shfl_xor_sync(0xffffffffu, a1.z, 16);
    a1.w += __shfl_xor_sync(0xffffffffu, a1.w, 16);

    if (half == 0) {
        float inv = g_inv[w];
        __half2 p0 = __floats2half2_rn(a0.x * inv, a0.y * inv);
        __half2 p1 = __floats2half2_rn(a0.z * inv, a0.w * inv);
        __half2 p2 = __floats2half2_rn(a1.x * inv, a1.y * inv);
        __half2 p3 = __floats2half2_rn(a1.z * inv, a1.w * inv);
        *(uint4*)(aout + (size_t)w * D + 8 * li) =
            make_uint4(*(unsigned*)&p0, *(unsigned*)&p1,
                       *(unsigned*)&p2, *(unsigned*)&p3);
    }
}

// ---------------- tensor-core GEMM (proven shape: BK=32, 256 thr, 8 warps) ----------------
// out[m][o] = [relu]( sum_k A[m][k]*Wl[o][k] + H[m][k]*Wr[o][k] + b[o] )
// Block 128x128, warp tile 32x64. 8 chunks (2 src x 4 k).
__global__ __launch_bounds__(256)
void gemm_kernel(const __half* __restrict__ Agg, const __half* __restrict__ Act,
                 const __half* __restrict__ Wl, const __half* __restrict__ Wr,
                 const float* __restrict__ bias,
                 float* __restrict__ out, __half* __restrict__ actout,
                 int n, int relu, int fin) {
    extern __shared__ char smraw[];
    float* Csm = (float*)smraw;

    int tid = threadIdx.x;
    int wid = tid >> 5;
    int warp_m = wid & 3;
    int warp_n = wid >> 2;
    int m0 = blockIdx.x * 128;

    wmma::fragment<wmma::accumulator, 16, 16, 16, float> acc[2][4];
    #pragma unroll
    for (int i = 0; i < 2; ++i)
        #pragma unroll
        for (int j = 0; j < 4; ++j) wmma::fill_fragment(acc[i][j], 0.0f);

    int lrow = tid >> 1;          // 0..127
    int lcol = (tid & 1) * 16;    // 0 or 16
    int grow = m0 + lrow;
    int arow = (grow < n) ? grow : (n - 1);   // clamp; garbage rows dropped in epilogue
    unsigned soff = (unsigned)(lrow * TSTRIDE + lcol) * 2;
    unsigned sbase = smem_u32(smraw);

    #define ISSUE(c, b) do {                                                   \
        int s_ = (c) >> 2, k0_ = ((c) & 3) * BK;                               \
        const __half* a_ = s_ ? Act : Agg;                                     \
        const __half* w_ = s_ ? Wr  : Wl;                                      \
        unsigned bb_ = sbase + (b) * BUF_BYTES;                                \
        size_t ga_ = (size_t)arow * D + k0_ + lcol;                            \
        size_t gw_ = (size_t)lrow * D + k0_ + lcol;                            \
        cp16(bb_ + 0 * TILE_BYTES + soff,      a_ + ga_);                      \
        cp16(bb_ + 0 * TILE_BYTES + soff + 16, a_ + ga_ + 8);                  \
        cp16(bb_ + 1 * TILE_BYTES + soff,      w_ + gw_);                      \
        cp16(bb_ + 1 * TILE_BYTES + soff + 16, w_ + gw_ + 8);                  \
        asm volatile("cp.async.commit_group;");                                \
    } while (0)

    ISSUE(0, 0);

    for (int c = 0; c < 8; ++c) {
        asm volatile("cp.async.wait_group 0;");
        __syncthreads();
        if (c < 7) ISSUE(c + 1, (c + 1) & 1);

        char* bb = smraw + (c & 1) * BUF_BYTES;
        __half* As = (__half*)(bb + 0 * TILE_BYTES);
        __half* Ws = (__half*)(bb + 1 * TILE_BYTES);

        #pragma unroll
        for (int kk = 0; kk < BK; kk += 16) {
            wmma::fragment<wmma::matrix_a, 16, 16, 16, __half, wmma::row_major> a[2];
            #pragma unroll
            for (int i = 0; i < 2; ++i)
                wmma::load_matrix_sync(a[i], As + (warp_m * 32 + i * 16) * TSTRIDE + kk, TSTRIDE);
            #pragma unroll
            for (int j = 0; j < 4; ++j) {
                wmma::fragment<wmma::matrix_b, 16, 16, 16, __half, wmma::col_major> b;
                wmma::load_matrix_sync(b, Ws + (warp_n * 64 + j * 16) * TSTRIDE + kk, TSTRIDE);
                #pragma unroll
                for (int i = 0; i < 2; ++i)
                    wmma::mma_sync(acc[i][j], a[i], b, acc[i][j]);
            }
        }
    }
    __syncthreads();
    #pragma unroll
    for (int i = 0; i < 2; ++i)
        #pragma unroll
        for (int j = 0; j < 4; ++j)
            wmma::store_matrix_sync(Csm + (warp_m * 32 + i * 16) * 128 + warp_n * 64 + j * 16,
                                    acc[i][j], 128, wmma::mem_row_major);
    __syncthreads();

    #pragma unroll
    for (int it = 0; it < 16; ++it) {
        int e = (it * 256 + tid) * 4;
        int row = e >> 7;
        int col = e & 127;
        int gr = m0 + row;
        if (gr >= n) continue;
        float4 v = *(float4*)(Csm + e);
        float4 b = *(const float4*)(bias + col);
        v.x += b.x; v.y += b.y; v.z += b.z; v.w += b.w;
        if (relu) {
            v.x = fmaxf(v.x, 0.f); v.y = fmaxf(v.y, 0.f);
            v.z = fmaxf(v.z, 0.f); v.w = fmaxf(v.w, 0.f);
        }
        size_t go = (size_t)gr * D + col;
        if (fin) {
            *(float4*)(out + go) = v;
        } else {
            __half2 a0 = __floats2half2_rn(v.x, v.y);
            __half2 a1 = __floats2half2_rn(v.z, v.w);
            *(uint2*)(actout + go) = make_uint2(*(unsigned*)&a0, *(unsigned*)&a1);
        }
    }
}

// ---------------- launch ----------------
extern "C" void kernel_launch(void* const* d_in, const int* in_sizes, int n_in,
                              void* d_out, int out_size) {
    const float* x   = (const float*)d_in[0];
    const void*  ei  = d_in[1];
    const float* W1l = (const float*)d_in[2];
    const float* b1  = (const float*)d_in[3];
    const float* W1r = (const float*)d_in[4];
    const float* W2l = (const float*)d_in[5];
    const float* b2  = (const float*)d_in[6];
    const float* W2r = (const float*)d_in[7];
    const float* W3l = (const float*)d_in[8];
    const float* b3  = (const float*)d_in[9];
    const float* W3r = (const float*)d_in[10];
    float* out = (float*)d_out;

    int n = in_sizes[0] / D;
    int E = in_sizes[1] / 2;

    __half *actp, *aggp, *wp;
    int *cntp, *totp;
    cudaGetSymbolAddress((void**)&actp, g_act);
    cudaGetSymbolAddress((void**)&aggp, g_agg);
    cudaGetSymbolAddress((void**)&wp,   g_W);
    cudaGetSymbolAddress((void**)&cntp, g_cnt);
    cudaGetSymbolAddress((void**)&totp, g_tot);

    cudaFuncSetAttribute(gemm_kernel, cudaFuncAttributeMaxDynamicSharedMemorySize, SMEM_TOTAL);

    // CSR build
    detect_kernel<<<1, 256>>>(ei, E);
    cudaMemsetAsync(cntp, 0, (size_t)n * sizeof(int));
    cudaMemsetAsync(totp, 0, sizeof(int));
    int e4 = (E + 3) / 4;
    hist_kernel<<<(e4 + 255) / 256, 256>>>(ei, E);
    assign_kernel<<<(n + 255) / 256, 256>>>(n);
    fill_kernel<<<(e4 + 255) / 256, 256>>>(ei, E);

    // conversions (weights + x in one launch)
    int total4 = n * D / 4;
    int conv_threads = 6 * D * D + total4;
    conv_kernel<<<(conv_threads + 255) / 256, 256>>>(x, actp, total4,
                                                     W1l, W1r, W2l, W2r, W3l, W3r);

    int agg_blocks  = (n * 32 + 255) / 256;
    int gemm_blocks = (n + 127) / 128;

    // layer 1
    agg_kernel<<<agg_blocks, 256>>>(actp, aggp, n);
    gemm_kernel<<<gemm_blocks, 256, SMEM_TOTAL>>>(aggp, actp,
        wp + 0 * D * D, wp + 1 * D * D, b1, out, actp, n, 1, 0);
    // layer 2
    agg_kernel<<<agg_blocks, 256>>>(actp, aggp, n);
    gemm_kernel<<<gemm_blocks, 256, SMEM_TOTAL>>>(aggp, actp,
        wp + 2 * D * D, wp + 3 * D * D, b2, out, actp, n, 1, 0);
    // layer 3 (final: fp32 out)
    agg_kernel<<<agg_blocks, 256>>>(actp, aggp, n);
    gemm_kernel<<<gemm_blocks, 256, SMEM_TOTAL>>>(aggp, actp,
        wp + 4 * D * D, wp + 5 * D * D, b3, out, actp, n, 0, 1);
}

// round 13
// speedup vs baseline: 1.5800x; 1.1207x over previous
#include <cuda_runtime.h>
#include <cuda_fp16.h>
#include <cuda_bf16.h>
#include <mma.h>
#include <stdint.h>

using namespace nvcuda;

// ---------------- problem constants ----------------
#define NMAX 50000
#define EMAX 800000
#define D    128
#define TSTRIDE 40        // smem tile stride (halves): 80B rows
#define BK 32
#define TILE_BYTES (128 * TSTRIDE * 2)      // 10240 B per fp16 tile
#define BUF_BYTES  (2 * TILE_BYTES)         // 20480 B per stage (A, W)
#define SMEM_TOTAL 65536                    // Csm (128*128*4) dominates
#define PREP_BLOCKS 592                     // 4/SM x 148 SMs — all co-resident

// ---------------- device scratch ----------------
__device__ int   g_ctrl[2];   // [0]=grid barrier counter, [1]=tot (memset per call)
__device__ int   g_cnt[NMAX];
__device__ int   g_rp[NMAX];
__device__ float g_inv[NMAX];
__device__ int   g_col[EMAX];
__device__ int   g_slot[EMAX];
__device__ int   g_is64;
__device__ __align__(16) __half g_act[NMAX * D];   // fp16 activations
__device__ __align__(16) __half g_agg[NMAX * D];   // fp16 aggregated means
__device__ __align__(16) __half g_W[6 * D * D];    // fp16 weights

// ---------------- helpers ----------------
__device__ __forceinline__ unsigned smem_u32(const void* p) {
    unsigned a;
    asm("{ .reg .u64 t; cvta.to.shared.u64 t, %1; cvt.u32.u64 %0, t; }"
        : "=r"(a) : "l"(p));
    return a;
}

__device__ __forceinline__ void cp16(unsigned sdst, const void* gsrc) {
    asm volatile("cp.async.cg.shared.global [%0], [%1], 16;"
                 :: "r"(sdst), "l"(gsrc));
}

// software grid barrier (all PREP_BLOCKS co-resident by construction)
__device__ __forceinline__ void grid_bar(int target) {
    __syncthreads();
    if (threadIdx.x == 0) {
        __threadfence();
        atomicAdd(&g_ctrl[0], 1);
        while (((volatile int*)g_ctrl)[0] < target) { }
        __threadfence();
    }
    __syncthreads();
}

__device__ __forceinline__ int load_idx2(const void* ei, long long pos, int is64) {
    if (is64) return (int)((const long long*)ei)[pos];
    return ((const int*)ei)[pos];
}

// ---------------- fused prep: detect + zero + conv + hist + assign + fill ----------------
__global__ __launch_bounds__(256, 4)
void prep_kernel(const void* ei, int E, int n,
                 const float* __restrict__ x, __half* __restrict__ act, int total4,
                 const float* __restrict__ w0, const float* __restrict__ w1,
                 const float* __restrict__ w2, const float* __restrict__ w3,
                 const float* __restrict__ w4, const float* __restrict__ w5) {
    int gtid = blockIdx.x * blockDim.x + threadIdx.x;
    int NT = gridDim.x * blockDim.x;
    int lane = threadIdx.x & 31;

    // ---- phase A: dtype detect (block 0), zero counts, convert W + x ----
    if (blockIdx.x == 0) {
        const int* p = (const int*)ei;
        int m = min(E, 2048);
        int bad = 0;
        for (int i = threadIdx.x; i < m; i += blockDim.x) bad |= p[2 * i + 1];
        __shared__ int s;
        if (threadIdx.x == 0) s = 0;
        __syncthreads();
        atomicOr(&s, bad);
        __syncthreads();
        if (threadIdx.x == 0) g_is64 = (s == 0) ? 1 : 0;
    }
    for (int i = gtid; i < n; i += NT) g_cnt[i] = 0;
    for (int i = gtid; i < 6 * D * D; i += NT) {
        int m = i >> 14, off = i & (D * D - 1);
        const float* src;
        switch (m) {
            case 0: src = w0; break; case 1: src = w1; break;
            case 2: src = w2; break; case 3: src = w3; break;
            case 4: src = w4; break; default: src = w5; break;
        }
        g_W[i] = __float2half_rn(src[off]);
    }
    for (int j = gtid; j < total4; j += NT) {
        float4 v = *(const float4*)(x + 4 * j);
        __half2 a0 = __floats2half2_rn(v.x, v.y);
        __half2 a1 = __floats2half2_rn(v.z, v.w);
        *(uint2*)(act + 4 * j) = make_uint2(*(unsigned*)&a0, *(unsigned*)&a1);
    }
    grid_bar(1 * (int)gridDim.x);

    // ---- phase B: hist (count + record slot) ----
    int is64 = __ldcg(&g_is64);
    int e4 = (E + 3) / 4;
    for (int g = gtid; g < e4; g += NT) {
        int e0 = 4 * g;
        int cnt = min(4, E - e0);
        int d[4], sl[4];
        #pragma unroll
        for (int i = 0; i < 4; ++i)
            if (i < cnt) d[i] = load_idx2(ei, (long long)E + e0 + i, is64);
        #pragma unroll
        for (int i = 0; i < 4; ++i)
            if (i < cnt) sl[i] = atomicAdd(&g_cnt[d[i]], 1);
        #pragma unroll
        for (int i = 0; i < 4; ++i)
            if (i < cnt) g_slot[e0 + i] = sl[i];
    }
    grid_bar(2 * (int)gridDim.x);

    // ---- phase C: assign (warp scan + global cursor) ----
    for (int i = gtid; i < ((n + NT - 1) / NT) * NT; i += NT) {
        int c = (i < n) ? __ldcg(&g_cnt[i]) : 0;
        int xv = c;
        #pragma unroll
        for (int off = 1; off < 32; off <<= 1) {
            int y = __shfl_up_sync(0xffffffffu, xv, off);
            if (lane >= off) xv += y;
        }
        int wsum = __shfl_sync(0xffffffffu, xv, 31);
        int base = 0;
        if (lane == 31) base = atomicAdd(&g_ctrl[1], wsum);
        base = __shfl_sync(0xffffffffu, base, 31);
        int excl = base + xv - c;
        if (i < n) {
            g_rp[i]  = excl;
            g_inv[i] = 1.0f / ((c > 0) ? (float)c : 1.0f);
        }
    }
    grid_bar(3 * (int)gridDim.x);

    // ---- phase D: fill (no atomics) ----
    for (int g = gtid; g < e4; g += NT) {
        int e0 = 4 * g;
        int cnt = min(4, E - e0);
        int s[4], d[4], sl[4], rp[4];
        #pragma unroll
        for (int i = 0; i < 4; ++i)
            if (i < cnt) {
                s[i]  = load_idx2(ei, e0 + i, is64);
                d[i]  = load_idx2(ei, (long long)E + e0 + i, is64);
                sl[i] = __ldcg(&g_slot[e0 + i]);
            }
        #pragma unroll
        for (int i = 0; i < 4; ++i)
            if (i < cnt) rp[i] = __ldcg(&g_rp[d[i]]);
        #pragma unroll
        for (int i = 0; i < 4; ++i)
            if (i < cnt) g_col[rp[i] + sl[i]] = s[i];
    }
}

// ---------------- mean aggregation (round-9 proven: LDG.64, fp32 accumulate) ----------------
__device__ __forceinline__ void acc_add(float4& acc, uint2 v) {
    __half2 h0 = *(__half2*)&v.x;
    __half2 h1 = *(__half2*)&v.y;
    float2 f0 = __half22float2(h0);
    float2 f1 = __half22float2(h1);
    acc.x += f0.x; acc.y += f0.y; acc.z += f1.x; acc.w += f1.y;
}

__global__ void agg_kernel(const __half* __restrict__ hin,
                           __half* __restrict__ aout, int n) {
    int w = (blockIdx.x * blockDim.x + threadIdx.x) >> 5;
    int lane = threadIdx.x & 31;
    if (w >= n) return;
    int start = g_rp[w];
    int end = start + g_cnt[w];
    float4 acc = make_float4(0.f, 0.f, 0.f, 0.f);
    for (int e = start; e < end; e += 32) {
        int myc = (e + lane < end) ? g_col[e + lane] : 0;
        int m = min(32, end - e);
        int j = 0;
        for (; j + 4 <= m; j += 4) {
            int s0 = __shfl_sync(0xffffffffu, myc, j + 0);
            int s1 = __shfl_sync(0xffffffffu, myc, j + 1);
            int s2 = __shfl_sync(0xffffffffu, myc, j + 2);
            int s3 = __shfl_sync(0xffffffffu, myc, j + 3);
            uint2 v0 = *(const uint2*)(hin + (size_t)s0 * D + 4 * lane);
            uint2 v1 = *(const uint2*)(hin + (size_t)s1 * D + 4 * lane);
            uint2 v2 = *(const uint2*)(hin + (size_t)s2 * D + 4 * lane);
            uint2 v3 = *(const uint2*)(hin + (size_t)s3 * D + 4 * lane);
            acc_add(acc, v0); acc_add(acc, v1);
            acc_add(acc, v2); acc_add(acc, v3);
        }
        for (; j < m; ++j) {
            int s = __shfl_sync(0xffffffffu, myc, j);
            uint2 v = *(const uint2*)(hin + (size_t)s * D + 4 * lane);
            acc_add(acc, v);
        }
    }
    float inv = g_inv[w];
    __half2 p0 = __floats2half2_rn(acc.x * inv, acc.y * inv);
    __half2 p1 = __floats2half2_rn(acc.z * inv, acc.w * inv);
    *(uint2*)(aout + (size_t)w * D + 4 * lane) = make_uint2(*(unsigned*)&p0, *(unsigned*)&p1);
}

// ---------------- tensor-core GEMM (proven shape: BK=32, 256 thr, 8 warps) ----------------
// out[m][o] = [relu]( sum_k A[m][k]*Wl[o][k] + H[m][k]*Wr[o][k] + b[o] )
__global__ __launch_bounds__(256)
void gemm_kernel(const __half* __restrict__ Agg, const __half* __restrict__ Act,
                 const __half* __restrict__ Wl, const __half* __restrict__ Wr,
                 const float* __restrict__ bias,
                 float* __restrict__ out, __half* __restrict__ actout,
                 int n, int relu, int fin) {
    extern __shared__ char smraw[];
    float* Csm = (float*)smraw;

    int tid = threadIdx.x;
    int wid = tid >> 5;
    int warp_m = wid & 3;
    int warp_n = wid >> 2;
    int m0 = blockIdx.x * 128;

    wmma::fragment<wmma::accumulator, 16, 16, 16, float> acc[2][4];
    #pragma unroll
    for (int i = 0; i < 2; ++i)
        #pragma unroll
        for (int j = 0; j < 4; ++j) wmma::fill_fragment(acc[i][j], 0.0f);

    int lrow = tid >> 1;          // 0..127
    int lcol = (tid & 1) * 16;    // 0 or 16
    int grow = m0 + lrow;
    int arow = (grow < n) ? grow : (n - 1);   // clamp; garbage rows dropped in epilogue
    unsigned soff = (unsigned)(lrow * TSTRIDE + lcol) * 2;
    unsigned sbase = smem_u32(smraw);

    #define ISSUE(c, b) do {                                                   \
        int s_ = (c) >> 2, k0_ = ((c) & 3) * BK;                               \
        const __half* a_ = s_ ? Act : Agg;                                     \
        const __half* w_ = s_ ? Wr  : Wl;                                      \
        unsigned bb_ = sbase + (b) * BUF_BYTES;                                \
        size_t ga_ = (size_t)arow * D + k0_ + lcol;                            \
        size_t gw_ = (size_t)lrow * D + k0_ + lcol;                            \
        cp16(bb_ + 0 * TILE_BYTES + soff,      a_ + ga_);                      \
        cp16(bb_ + 0 * TILE_BYTES + soff + 16, a_ + ga_ + 8);                  \
        cp16(bb_ + 1 * TILE_BYTES + soff,      w_ + gw_);                      \
        cp16(bb_ + 1 * TILE_BYTES + soff + 16, w_ + gw_ + 8);                  \
        asm volatile("cp.async.commit_group;");                                \
    } while (0)

    ISSUE(0, 0);

    for (int c = 0; c < 8; ++c) {
        asm volatile("cp.async.wait_group 0;");
        __syncthreads();
        if (c < 7) ISSUE(c + 1, (c + 1) & 1);

        char* bb = smraw + (c & 1) * BUF_BYTES;
        __half* As = (__half*)(bb + 0 * TILE_BYTES);
        __half* Ws = (__half*)(bb + 1 * TILE_BYTES);

        #pragma unroll
        for (int kk = 0; kk < BK; kk += 16) {
            wmma::fragment<wmma::matrix_a, 16, 16, 16, __half, wmma::row_major> a[2];
            #pragma unroll
            for (int i = 0; i < 2; ++i)
                wmma::load_matrix_sync(a[i], As + (warp_m * 32 + i * 16) * TSTRIDE + kk, TSTRIDE);
            #pragma unroll
            for (int j = 0; j < 4; ++j) {
                wmma::fragment<wmma::matrix_b, 16, 16, 16, __half, wmma::col_major> b;
                wmma::load_matrix_sync(b, Ws + (warp_n * 64 + j * 16) * TSTRIDE + kk, TSTRIDE);
                #pragma unroll
                for (int i = 0; i < 2; ++i)
                    wmma::mma_sync(acc[i][j], a[i], b, acc[i][j]);
            }
        }
    }
    __syncthreads();
    #pragma unroll
    for (int i = 0; i < 2; ++i)
        #pragma unroll
        for (int j = 0; j < 4; ++j)
            wmma::store_matrix_sync(Csm + (warp_m * 32 + i * 16) * 128 + warp_n * 64 + j * 16,
                                    acc[i][j], 128, wmma::mem_row_major);
    __syncthreads();

    #pragma unroll
    for (int it = 0; it < 16; ++it) {
        int e = (it * 256 + tid) * 4;
        int row = e >> 7;
        int col = e & 127;
        int gr = m0 + row;
        if (gr >= n) continue;
        float4 v = *(float4*)(Csm + e);
        float4 b = *(const float4*)(bias + col);
        v.x += b.x; v.y += b.y; v.z += b.z; v.w += b.w;
        if (relu) {
            v.x = fmaxf(v.x, 0.f); v.y = fmaxf(v.y, 0.f);
            v.z = fmaxf(v.z, 0.f); v.w = fmaxf(v.w, 0.f);
        }
        size_t go = (size_t)gr * D + col;
        if (fin) {
            *(float4*)(out + go) = v;
        } else {
            __half2 a0 = __floats2half2_rn(v.x, v.y);
            __half2 a1 = __floats2half2_rn(v.z, v.w);
            *(uint2*)(actout + go) = make_uint2(*(unsigned*)&a0, *(unsigned*)&a1);
        }
    }
}

// ---------------- launch ----------------
extern "C" void kernel_launch(void* const* d_in, const int* in_sizes, int n_in,
                              void* d_out, int out_size) {
    const float* x   = (const float*)d_in[0];
    const void*  ei  = d_in[1];
    const float* W1l = (const float*)d_in[2];
    const float* b1  = (const float*)d_in[3];
    const float* W1r = (const float*)d_in[4];
    const float* W2l = (const float*)d_in[5];
    const float* b2  = (const float*)d_in[6];
    const float* W2r = (const float*)d_in[7];
    const float* W3l = (const float*)d_in[8];
    const float* b3  = (const float*)d_in[9];
    const float* W3r = (const float*)d_in[10];
    float* out = (float*)d_out;

    int n = in_sizes[0] / D;
    int E = in_sizes[1] / 2;

    __half *actp, *aggp, *wp;
    int *ctrlp;
    cudaGetSymbolAddress((void**)&actp,  g_act);
    cudaGetSymbolAddress((void**)&aggp,  g_agg);
    cudaGetSymbolAddress((void**)&wp,    g_W);
    cudaGetSymbolAddress((void**)&ctrlp, g_ctrl);

    cudaFuncSetAttribute(gemm_kernel, cudaFuncAttributeMaxDynamicSharedMemorySize, SMEM_TOTAL);

    // reset barrier counter + segment cursor, then fused prep
    cudaMemsetAsync(ctrlp, 0, 2 * sizeof(int));
    int total4 = n * D / 4;
    prep_kernel<<<PREP_BLOCKS, 256>>>(ei, E, n, x, actp, total4,
                                      W1l, W1r, W2l, W2r, W3l, W3r);

    int agg_blocks  = (n * 32 + 255) / 256;
    int gemm_blocks = (n + 127) / 128;

    // layer 1
    agg_kernel<<<agg_blocks, 256>>>(actp, aggp, n);
    gemm_kernel<<<gemm_blocks, 256, SMEM_TOTAL>>>(aggp, actp,
        wp + 0 * D * D, wp + 1 * D * D, b1, out, actp, n, 1, 0);
    // layer 2
    agg_kernel<<<agg_blocks, 256>>>(actp, aggp, n);
    gemm_kernel<<<gemm_blocks, 256, SMEM_TOTAL>>>(aggp, actp,
        wp + 2 * D * D, wp + 3 * D * D, b2, out, actp, n, 1, 0);
    // layer 3 (final: fp32 out)
    agg_kernel<<<agg_blocks, 256>>>(actp, aggp, n);
    gemm_kernel<<<gemm_blocks, 256, SMEM_TOTAL>>>(aggp, actp,
        wp + 4 * D * D, wp + 5 * D * D, b3, out, actp, n, 0, 1);
}